// round 4
// baseline (speedup 1.0000x reference)
#include <cuda_runtime.h>
#include <cuda_bf16.h>
#include <cstdint>

// ---------------------------------------------------------------------------
// AdaptiveEMAModel. Key ideas:
//  * k_t is a pure function of the vocab id -> compute FFN/LN/kproj over the
//    32000-row vocab table (4.1x fewer flops). The scan reads the tables
//    DIRECTLY through L2 (no per-token gather streams at all).
//  * fp32 everywhere (fire gate is discontinuous), packed fma.rn.f32x2
//    (SASS FFMA2) for 2x fp32 throughput.
//  * Scan: 4x16 thread tiles over M (8x less LDS traffic), lag-2 lazy update
//    + precomputed adjacent Gram g1[t] = kn_{t-1}.kn_t so the ||d||^2 block
//    reduction resolves one step late, off the critical path.
// ---------------------------------------------------------------------------

typedef unsigned long long u64t;

__device__ __forceinline__ u64t pk2(float lo, float hi) {
    u64t r;
    asm("mov.b64 %0, {%1, %2};" : "=l"(r) : "f"(lo), "f"(hi));
    return r;
}
__device__ __forceinline__ void fma2(u64t& d, u64t a, u64t b) {
    asm("fma.rn.f32x2 %0, %1, %2, %0;" : "+l"(d) : "l"(a), "l"(b));
}
__device__ __forceinline__ void addf2(u64t& d, u64t a) {
    asm("add.rn.f32x2 %0, %0, %1;" : "+l"(d) : "l"(a));
}
__device__ __forceinline__ float2 upk(u64t v) {
    float2 f;
    asm("mov.b64 {%0, %1}, %2;" : "=f"(f.x), "=f"(f.y) : "l"(v));
    return f;
}
__device__ __forceinline__ float hsum(u64t v) {
    float2 f = upk(v);
    return f.x + f.y;
}

#define Bn   64
#define Ln   2048
#define Hn   128
#define H2n  256
#define Vn   32000
#define NTOK (Bn * Ln)

// ------------------------- global scratch ----------------------------------
__device__ __align__(16) float g_y[(size_t)Vn * H2n];      // 32.8 MB
__device__ __align__(16) float g_hln[(size_t)Vn * Hn];     // 16.4 MB
__device__ __align__(16) float g_Kv[(size_t)Vn * Hn];      // raw k per vocab
__device__ __align__(16) float g_KNv[(size_t)Vn * Hn];     // normalized k
__device__ __align__(16) float g_THv[Vn];                  // (0.4*||k||)^2
__device__ __align__(16) float g_g1[NTOK];                 // kn_{t-1}.kn_t
__device__ __align__(16) float g_read[Bn * Hn];
__device__ __align__(16) float g_r2[Bn * Hn];
__device__ int g_is64;

// ------------------------- K0: detect seq dtype ----------------------------
__global__ void k0_detect(const unsigned int* __restrict__ sw) {
    int t = threadIdx.x;
    int nz = (sw[2 * t + 1] != 0u) ? 1 : 0;
    nz = __syncthreads_or(nz);
    if (t == 0) g_is64 = nz ? 0 : 1;
}

// ------------------------- KV1: FFN layer 1 over vocab ---------------------
#define KV1_SMEM ((256 * 132 + 32 * 132) * 4)

__global__ __launch_bounds__(256, 1)
void kv1(const float* __restrict__ ew,
         const float* __restrict__ w1, const float* __restrict__ b1) {
    extern __shared__ float sm[];
    float* W = sm;                // 256 x 132
    float* X = sm + 256 * 132;    // 32 x 132

    const int tid = threadIdx.x;
    const int lane = tid & 31;
    const int w = tid >> 5;
    const int tg = (w & 3) * 8;
    const int ob = (w >> 2) * 4;

    for (int i = tid; i < 256 * 32; i += 256) {
        int r = i >> 5, c = i & 31;
        *(float4*)(W + r * 132 + 4 * c) = *(const float4*)(w1 + r * 128 + 4 * c);
    }
    float bb[4];
#pragma unroll
    for (int j = 0; j < 4; ++j) bb[j] = b1[lane + 32 * (ob + j)];
    __syncthreads();

    const float4* W4 = (const float4*)W;
    const float4* X4 = (const float4*)X;

    for (int tile = blockIdx.x; tile < Vn / 32; tile += gridDim.x) {
        const int v0 = tile * 32;
        for (int i = tid; i < 32 * 32; i += 256) {
            int tk = i >> 5, q = i & 31;
            *(float4*)(X + tk * 132 + 4 * q) = *(const float4*)(ew + (size_t)(v0 + tk) * 128 + 4 * q);
        }
        __syncthreads();

        u64t acc[8][4];
#pragma unroll
        for (int i = 0; i < 8; ++i)
#pragma unroll
            for (int j = 0; j < 4; ++j) acc[i][j] = 0ull;

#pragma unroll 4
        for (int hh = 0; hh < 32; ++hh) {
            u64t wl[4], wh[4];
#pragma unroll
            for (int j = 0; j < 4; ++j) {
                float4 wq = W4[(lane + 32 * (ob + j)) * 33 + hh];
                wl[j] = pk2(wq.x, wq.y);
                wh[j] = pk2(wq.z, wq.w);
            }
#pragma unroll
            for (int i = 0; i < 8; ++i) {
                float4 xq = X4[(tg + i) * 33 + hh];
                u64t xl = pk2(xq.x, xq.y), xh = pk2(xq.z, xq.w);
#pragma unroll
                for (int j = 0; j < 4; ++j) {
                    fma2(acc[i][j], xl, wl[j]);
                    fma2(acc[i][j], xh, wh[j]);
                }
            }
        }
#pragma unroll
        for (int i = 0; i < 8; ++i)
#pragma unroll
            for (int j = 0; j < 4; ++j) {
                float y = hsum(acc[i][j]) + bb[j];
                g_y[(size_t)(v0 + tg + i) * H2n + lane + 32 * (ob + j)] = fmaxf(y, 0.0f);
            }
        __syncthreads();
    }
}

// ------------------------- KV2: FFN layer 2 + residual + LN over vocab -----
#define KV2_SMEM ((128 * 260 + 64 * 260) * 4)

__global__ __launch_bounds__(256, 1)
void kv2(const float* __restrict__ ew,
         const float* __restrict__ w2, const float* __restrict__ b2,
         const float* __restrict__ lng, const float* __restrict__ lnb) {
    extern __shared__ float sm[];
    float* W = sm;                // 128 x 260
    float* Y = sm + 128 * 260;    // 64 x 260

    const int tid = threadIdx.x;
    const int lane = tid & 31;
    const int w = tid >> 5;
    const int tg = w * 8;

    for (int i = tid; i < 128 * 64; i += 256) {
        int r = i >> 6, c = i & 63;
        *(float4*)(W + r * 260 + 4 * c) = *(const float4*)(w2 + r * 256 + 4 * c);
    }
    float b2r[4], gr[4], br[4];
#pragma unroll
    for (int j = 0; j < 4; ++j) {
        b2r[j] = b2[lane + 32 * j];
        gr[j] = lng[lane + 32 * j];
        br[j] = lnb[lane + 32 * j];
    }
    __syncthreads();

    const float4* W4 = (const float4*)W;
    const float4* Y4 = (const float4*)Y;

    for (int tile = blockIdx.x; tile < Vn / 64; tile += gridDim.x) {
        const int v0 = tile * 64;
        for (int i = tid; i < 64 * 64; i += 256) {
            int tk = i >> 6, c = i & 63;
            *(float4*)(Y + tk * 260 + 4 * c) = *(const float4*)(g_y + (size_t)(v0 + tk) * H2n + 4 * c);
        }
        __syncthreads();

        u64t acc[8][4];
#pragma unroll
        for (int i = 0; i < 8; ++i)
#pragma unroll
            for (int j = 0; j < 4; ++j) acc[i][j] = 0ull;

#pragma unroll 2
        for (int oo = 0; oo < 64; ++oo) {
            u64t wl[4], wh[4];
#pragma unroll
            for (int j = 0; j < 4; ++j) {
                float4 wq = W4[(lane + 32 * j) * 65 + oo];
                wl[j] = pk2(wq.x, wq.y);
                wh[j] = pk2(wq.z, wq.w);
            }
#pragma unroll
            for (int i = 0; i < 8; ++i) {
                float4 yq = Y4[(tg + i) * 65 + oo];
                u64t yl = pk2(yq.x, yq.y), yh = pk2(yq.z, yq.w);
#pragma unroll
                for (int j = 0; j < 4; ++j) {
                    fma2(acc[i][j], yl, wl[j]);
                    fma2(acc[i][j], yh, wh[j]);
                }
            }
        }

#pragma unroll
        for (int i = 0; i < 8; ++i) {
            const size_t tok = (size_t)(v0 + tg + i);
            float x[4];
#pragma unroll
            for (int j = 0; j < 4; ++j)
                x[j] = hsum(acc[i][j]) + b2r[j] + ew[tok * 128 + lane + 32 * j];
            float s = x[0] + x[1] + x[2] + x[3];
#pragma unroll
            for (int off = 16; off; off >>= 1) s += __shfl_xor_sync(0xffffffffu, s, off);
            float mu = s * (1.0f / 128.0f);
            float vs = 0.0f;
#pragma unroll
            for (int j = 0; j < 4; ++j) { float dv = x[j] - mu; vs += dv * dv; }
#pragma unroll
            for (int off = 16; off; off >>= 1) vs += __shfl_xor_sync(0xffffffffu, vs, off);
            float den = sqrtf(vs * (1.0f / 128.0f) + 1e-5f);
#pragma unroll
            for (int j = 0; j < 4; ++j)
                g_hln[tok * Hn + lane + 32 * j] = (x[j] - mu) / den * gr[j] + br[j];
        }
        __syncthreads();
    }
}

// ------------------------- KV3: kproj + norm/kn/threshold over vocab -------
#define KV3_SMEM ((128 * 132 + 64 * 132) * 4)

__global__ __launch_bounds__(256, 1)
void kv3(const float* __restrict__ kpw) {
    extern __shared__ float sm[];
    float* W = sm;                // 128 x 132
    float* X = sm + 128 * 132;    // 64 x 132

    const int tid = threadIdx.x;
    const int lane = tid & 31;
    const int w = tid >> 5;
    const int tg = w * 8;

    for (int i = tid; i < 128 * 32; i += 256) {
        int r = i >> 5, c = i & 31;
        *(float4*)(W + r * 132 + 4 * c) = *(const float4*)(kpw + r * 128 + 4 * c);
    }
    __syncthreads();

    const float4* W4 = (const float4*)W;
    const float4* X4 = (const float4*)X;

    for (int tile = blockIdx.x; tile < Vn / 64; tile += gridDim.x) {
        const int v0 = tile * 64;
        for (int i = tid; i < 64 * 32; i += 256) {
            int tk = i >> 5, q = i & 31;
            *(float4*)(X + tk * 132 + 4 * q) = *(const float4*)(g_hln + (size_t)(v0 + tk) * Hn + 4 * q);
        }
        __syncthreads();

        u64t acc[8][4];
#pragma unroll
        for (int i = 0; i < 8; ++i)
#pragma unroll
            for (int j = 0; j < 4; ++j) acc[i][j] = 0ull;

#pragma unroll 4
        for (int hh = 0; hh < 32; ++hh) {
            u64t wl[4], wh[4];
#pragma unroll
            for (int j = 0; j < 4; ++j) {
                float4 wq = W4[(lane + 32 * j) * 33 + hh];
                wl[j] = pk2(wq.x, wq.y);
                wh[j] = pk2(wq.z, wq.w);
            }
#pragma unroll
            for (int i = 0; i < 8; ++i) {
                float4 xq = X4[(tg + i) * 33 + hh];
                u64t xl = pk2(xq.x, xq.y), xh = pk2(xq.z, xq.w);
#pragma unroll
                for (int j = 0; j < 4; ++j) {
                    fma2(acc[i][j], xl, wl[j]);
                    fma2(acc[i][j], xh, wh[j]);
                }
            }
        }
#pragma unroll
        for (int i = 0; i < 8; ++i) {
            const size_t tok = (size_t)(v0 + tg + i);
            float kv[4];
            float s = 0.0f;
#pragma unroll
            for (int j = 0; j < 4; ++j) {
                kv[j] = hsum(acc[i][j]);
                g_Kv[tok * Hn + lane + 32 * j] = kv[j];
                s += kv[j] * kv[j];
            }
#pragma unroll
            for (int off = 16; off; off >>= 1) s += __shfl_xor_sync(0xffffffffu, s, off);
            float nm = fmaxf(sqrtf(s), 1e-12f);
#pragma unroll
            for (int j = 0; j < 4; ++j)
                g_KNv[tok * Hn + lane + 32 * j] = kv[j] / nm;
            if (lane == 0) {
                float t1 = 0.4f * nm;
                g_THv[tok] = t1 * t1;
            }
        }
        __syncthreads();
    }
}

// ------------------------- KGG: adjacent Gram g1[t] from tables ------------
__global__ void kgg(const void* __restrict__ seq) {
    const int lane = threadIdx.x & 31;
    const int w = threadIdx.x >> 5;
    const size_t gt = (size_t)blockIdx.x * 8 + w;
    const int t = (int)(gt & (Ln - 1));
    if (t == 0) {
        if (lane == 0) g_g1[gt] = 0.0f;
        return;
    }
    const int is64 = g_is64;
    long long i0 = is64 ? ((const long long*)seq)[gt - 1]
                        : (long long)((const int*)seq)[gt - 1];
    long long i1 = is64 ? ((const long long*)seq)[gt]
                        : (long long)((const int*)seq)[gt];
    float4 a = ((const float4*)g_KNv)[(size_t)i0 * 32 + lane];
    float4 c = ((const float4*)g_KNv)[(size_t)i1 * 32 + lane];
    float s = a.x * c.x + a.y * c.y + a.z * c.z + a.w * c.w;
#pragma unroll
    for (int off = 16; off; off >>= 1) s += __shfl_xor_sync(0xffffffffu, s, off);
    if (lane == 0) g_g1[gt] = s;
}

// ------------------------- K2: lazy delta-rule scan ------------------------
// 64 CTAs x 256 threads. Thread (rg, cg) owns M rows rg*4..+3, cols cg*16..+15
// (32 f32x2 regs). All k/kn reads go straight to the L2-resident vocab tables
// (idx sequence staged in smem). Lag-2 update + g1 correction as before.
__global__ __launch_bounds__(256, 1)
void k2_scan(const void* __restrict__ seq) {
    const int b = blockIdx.x;
    const int tid = threadIdx.x;
    const int lane = tid & 31;
    const int w = tid >> 5;
    const int cg = tid & 7;        // column group: cols cg*16..cg*16+15
    const int rg = tid >> 3;       // row group: rows rg*4..rg*4+3
    const int coff = cg * 16;
    const int roff = rg * 4;

    __shared__ int   idxs[Ln];
    __shared__ float ths[Ln];
    __shared__ float g1s[Ln];
    __shared__ __align__(16) float red[2][8];

    const int is64 = g_is64;
    for (int i = tid; i < Ln; i += 256) {
        long long idx = is64 ? ((const long long*)seq)[(size_t)b * Ln + i]
                             : (long long)((const int*)seq)[(size_t)b * Ln + i];
        idxs[i] = (int)idx;
        ths[i] = g_THv[idx];
        g1s[i] = g_g1[(size_t)b * Ln + i];
    }
    if (tid < 16) red[tid >> 3][tid & 7] = 0.0f;
    __syncthreads();

    const float* KN = g_KNv;
    const float* KR = g_Kv;

    u64t M[4][8];
#pragma unroll
    for (int i = 0; i < 4; ++i)
#pragma unroll
        for (int j = 0; j < 8; ++j) M[i][j] = 0ull;

    u64t knt[8], knt1[8];
    float kt[4], kt1[4];
    {
        const float* p0 = KN + (size_t)idxs[0] * Hn + coff;
        const float* p1 = KN + (size_t)idxs[1] * Hn + coff;
#pragma unroll
        for (int q = 0; q < 4; ++q) {
            float4 v0 = *(const float4*)(p0 + 4 * q);
            float4 v1 = *(const float4*)(p1 + 4 * q);
            knt[2 * q] = pk2(v0.x, v0.y);  knt[2 * q + 1] = pk2(v0.z, v0.w);
            knt1[2 * q] = pk2(v1.x, v1.y); knt1[2 * q + 1] = pk2(v1.z, v1.w);
        }
        float4 a = *(const float4*)(KR + (size_t)idxs[0] * Hn + roff);
        float4 c = *(const float4*)(KR + (size_t)idxs[1] * Hn + roff);
        kt[0] = a.x; kt[1] = a.y; kt[2] = a.z; kt[3] = a.w;
        kt1[0] = c.x; kt1[1] = c.y; kt1[2] = c.z; kt1[3] = c.w;
    }

    float dm1[4] = {0.f, 0.f, 0.f, 0.f};
    float s2[4]  = {0.f, 0.f, 0.f, 0.f};

#pragma unroll 2
    for (int t = 0; t < Ln - 1; ++t) {
        // ---- resolve fire_{t-1} (reduction finished last step) ----
        float s1[4];
        if (t > 0) {
            float4 r0 = *(const float4*)&red[(t + 1) & 1][0];
            float4 r1 = *(const float4*)&red[(t + 1) & 1][4];
            float dd = ((r0.x + r0.y) + (r0.z + r0.w)) + ((r1.x + r1.y) + (r1.z + r1.w));
            float fire = (dd >= ths[t - 1]) ? (1.0f / 2048.0f) : 0.0f;
#pragma unroll
            for (int i = 0; i < 4; ++i) s1[i] = dm1[i] * fire;
        } else {
#pragma unroll
            for (int i = 0; i < 4; ++i) s1[i] = 0.0f;
        }

        // ---- reload kn_{t-2} (L1-hot) for the lagged update ----
        const int tm2 = (t >= 2) ? t - 2 : 0;
        const float* pm2 = KN + (size_t)idxs[tm2] * Hn + coff;
        u64t knm2[8];
#pragma unroll
        for (int q = 0; q < 4; ++q) {
            float4 v = *(const float4*)(pm2 + 4 * q);
            knm2[2 * q] = pk2(v.x, v.y);
            knm2[2 * q + 1] = pk2(v.z, v.w);
        }

        // ---- fused: M += s_{t-2} (x) kn_{t-2} ; acc = M kn_t ----
        u64t acc[4];
#pragma unroll
        for (int i = 0; i < 4; ++i) {
            u64t s2p = pk2(s2[i], s2[i]);
            u64t a = 0ull;
#pragma unroll
            for (int j = 0; j < 8; ++j) {
                fma2(M[i][j], s2p, knm2[j]);
                fma2(a, M[i][j], knt[j]);
            }
            acc[i] = a;
        }

        // ---- vp butterfly over 8 col groups (packed f32x2) ----
        u64t vAB = pk2(hsum(acc[0]), hsum(acc[1]));
        u64t vCD = pk2(hsum(acc[2]), hsum(acc[3]));
#pragma unroll
        for (int off = 1; off <= 4; off <<= 1) {
            addf2(vAB, __shfl_xor_sync(0xffffffffu, vAB, off));
            addf2(vCD, __shfl_xor_sync(0xffffffffu, vCD, off));
        }
        float2 fAB = upk(vAB), fCD = upk(vCD);
        float vp[4] = {fAB.x, fAB.y, fCD.x, fCD.y};

        // ---- correction for the missing t-1 update, then d ----
        const float g1t = g1s[t];
        float d[4], dsq = 0.0f;
#pragma unroll
        for (int i = 0; i < 4; ++i) {
            float v = fmaf(s1[i], g1t, vp[i]);
            d[i] = kt[i] - v;
            dsq = fmaf(d[i], d[i], dsq);
        }
        // sum across the 4 row-groups of this warp (cols already replicated)
        dsq += __shfl_xor_sync(0xffffffffu, dsq, 8);
        dsq += __shfl_xor_sync(0xffffffffu, dsq, 16);
        if (lane == 0) red[t & 1][w] = dsq;

        // ---- rotate + prefetch t+2 (reads L2-resident tables) ----
#pragma unroll
        for (int j = 0; j < 8; ++j) knt[j] = knt1[j];
#pragma unroll
        for (int i = 0; i < 4; ++i) {
            dm1[i] = d[i];
            s2[i] = s1[i];
            kt[i] = kt1[i];
        }
        const int tp = (t + 2 <= Ln - 2) ? t + 2 : Ln - 2;
        const float* pkn = KN + (size_t)idxs[tp] * Hn + coff;
#pragma unroll
        for (int q = 0; q < 4; ++q) {
            float4 v = *(const float4*)(pkn + 4 * q);
            knt1[2 * q] = pk2(v.x, v.y);
            knt1[2 * q + 1] = pk2(v.z, v.w);
        }
        float4 kv = *(const float4*)(KR + (size_t)idxs[tp] * Hn + roff);
        kt1[0] = kv.x; kt1[1] = kv.y; kt1[2] = kv.z; kt1[3] = kv.w;

        __syncthreads();
    }

    // ---- finalize: apply s_{2045} and s_{2046}; read = M q (raw k_2047) ----
    {
        float4 r0 = *(const float4*)&red[(Ln - 2) & 1][0];
        float4 r1 = *(const float4*)&red[(Ln - 2) & 1][4];
        float dd = ((r0.x + r0.y) + (r0.z + r0.w)) + ((r1.x + r1.y) + (r1.z + r1.w));
        float fire = (dd >= ths[Ln - 2]) ? (1.0f / 2048.0f) : 0.0f;
        float sF[4];
#pragma unroll
        for (int i = 0; i < 4; ++i) sF[i] = dm1[i] * fire;

        const float* p45 = KN + (size_t)idxs[Ln - 3] * Hn + coff;
        const float* p46 = KN + (size_t)idxs[Ln - 2] * Hn + coff;
        const float* pq  = KR + (size_t)idxs[Ln - 1] * Hn + coff;
        u64t kn45[8], kn46[8], qv[8];
#pragma unroll
        for (int q = 0; q < 4; ++q) {
            float4 a = *(const float4*)(p45 + 4 * q);
            float4 c = *(const float4*)(p46 + 4 * q);
            float4 e = *(const float4*)(pq + 4 * q);
            kn45[2 * q] = pk2(a.x, a.y); kn45[2 * q + 1] = pk2(a.z, a.w);
            kn46[2 * q] = pk2(c.x, c.y); kn46[2 * q + 1] = pk2(c.z, c.w);
            qv[2 * q] = pk2(e.x, e.y);   qv[2 * q + 1] = pk2(e.z, e.w);
        }

        u64t acc[4];
#pragma unroll
        for (int i = 0; i < 4; ++i) {
            u64t sAp = pk2(s2[i], s2[i]);
            u64t sFp = pk2(sF[i], sF[i]);
            u64t a = 0ull;
#pragma unroll
            for (int j = 0; j < 8; ++j) {
                fma2(M[i][j], sAp, kn45[j]);
                fma2(M[i][j], sFp, kn46[j]);
                fma2(a, M[i][j], qv[j]);
            }
            acc[i] = a;
        }
        u64t vAB = pk2(hsum(acc[0]), hsum(acc[1]));
        u64t vCD = pk2(hsum(acc[2]), hsum(acc[3]));
#pragma unroll
        for (int off = 1; off <= 4; off <<= 1) {
            addf2(vAB, __shfl_xor_sync(0xffffffffu, vAB, off));
            addf2(vCD, __shfl_xor_sync(0xffffffffu, vCD, off));
        }
        if (cg == 0) {
            float2 fAB = upk(vAB), fCD = upk(vCD);
            g_read[b * Hn + roff + 0] = fAB.x;
            g_read[b * Hn + roff + 1] = fAB.y;
            g_read[b * Hn + roff + 2] = fCD.x;
            g_read[b * Hn + roff + 3] = fCD.y;
        }
    }
}

// ------------------------- K2b: r2 = read @ rp_w^T + rp_b ------------------
__global__ void k2b(const float* __restrict__ rpw, const float* __restrict__ rpb) {
    __shared__ __align__(16) float rs[128];
    const int b = blockIdx.x, tid = threadIdx.x;
    rs[tid] = g_read[b * Hn + tid];
    __syncthreads();
    const u64t* rp = (const u64t*)rs;
    u64t acc = 0ull;
#pragma unroll 8
    for (int j2 = 0; j2 < 64; ++j2) {
        u64t wv = *(const u64t*)(rpw + tid * 128 + 2 * j2);
        fma2(acc, rp[j2], wv);
    }
    g_r2[b * Hn + tid] = hsum(acc) + rpb[tid];
}

// ------------------------- K3: out = r2 @ out_w^T + out_b ------------------
#define K3_SMEM ((64 * 128 + 64 * 130) * 4)

__global__ __launch_bounds__(256, 1)
void k3(const float* __restrict__ ow, const float* __restrict__ ob,
        float* __restrict__ out) {
    extern __shared__ float sm[];
    float* r2s = sm;             // 64 x 128
    float* ws = sm + 64 * 128;   // 64 x 130

    const int tid = threadIdx.x;
    const int v0 = blockIdx.x * 64;

    for (int i = tid; i < 64 * 32; i += 256)
        ((float4*)r2s)[i] = ((const float4*)g_r2)[i];
    for (int i = tid; i < 64 * 64; i += 256) {
        int r = i >> 6, c = i & 63;
        *(float2*)(ws + r * 130 + 2 * c) = *(const float2*)(ow + (size_t)(v0 + r) * 128 + 2 * c);
    }
    __syncthreads();

    const int vl = tid & 63;
    const int bg = tid >> 6;
    const float obv = ob[v0 + vl];

#pragma unroll 4
    for (int bi = 0; bi < 16; ++bi) {
        int bb = bg * 16 + bi;
        u64t acc = 0ull;
#pragma unroll 16
        for (int h2 = 0; h2 < 64; ++h2)
            fma2(acc, *(const u64t*)(r2s + bb * 128 + 2 * h2),
                      *(const u64t*)(ws + vl * 130 + 2 * h2));
        out[(size_t)bb * Vn + v0 + vl] = hsum(acc) + obv;
    }
}

// ------------------------- launch ------------------------------------------
extern "C" void kernel_launch(void* const* d_in, const int* in_sizes, int n_in,
                              void* d_out, int out_size) {
    (void)in_sizes; (void)n_in; (void)out_size;
    const void*  seq = d_in[0];
    const float* ew  = (const float*)d_in[1];
    const float* w1  = (const float*)d_in[2];
    const float* b1  = (const float*)d_in[3];
    const float* w2  = (const float*)d_in[4];
    const float* b2  = (const float*)d_in[5];
    const float* lng = (const float*)d_in[6];
    const float* lnb = (const float*)d_in[7];
    const float* kpw = (const float*)d_in[8];
    const float* rpw = (const float*)d_in[9];
    const float* rpb = (const float*)d_in[10];
    const float* ow  = (const float*)d_in[11];
    const float* ob  = (const float*)d_in[12];
    float* out = (float*)d_out;

    cudaFuncSetAttribute(kv1, cudaFuncAttributeMaxDynamicSharedMemorySize, KV1_SMEM);
    cudaFuncSetAttribute(kv2, cudaFuncAttributeMaxDynamicSharedMemorySize, KV2_SMEM);
    cudaFuncSetAttribute(kv3, cudaFuncAttributeMaxDynamicSharedMemorySize, KV3_SMEM);
    cudaFuncSetAttribute(k3,  cudaFuncAttributeMaxDynamicSharedMemorySize, K3_SMEM);

    k0_detect<<<1, 256>>>((const unsigned int*)seq);
    kv1<<<148, 256, KV1_SMEM>>>(ew, w1, b1);
    kv2<<<148, 256, KV2_SMEM>>>(ew, w2, b2, lng, lnb);
    kv3<<<296, 256, KV3_SMEM>>>(kpw);
    kgg<<<NTOK / 8, 256>>>(seq);
    k2_scan<<<Bn, 256>>>(seq);
    k2b<<<Bn, 128>>>(rpw, rpb);
    k3<<<Vn / 64, 256, K3_SMEM>>>(ow, ob, out);
}